// round 3
// baseline (speedup 1.0000x reference)
#include <cuda_runtime.h>

#define NPTS 500000
#define K 256
#define D 64

// Copy centroids (echoed as first output of the tuple).
__global__ void copy_centroids_kernel(const float* __restrict__ c, float* __restrict__ out) {
    int i = blockIdx.x * blockDim.x + threadIdx.x;
    if (i < K * D) out[i] = c[i];
}

// Assignment kernel. One thread = one point.
// Replicates the reference arithmetic exactly:
//   d_sq[k] = (x_sq - 2*dot_k) + c_sq[k]
// with x_sq / c_sq = (rounded squares, sequential adds), dot_k = sequential FMA,
// so rounding noise is shared with the reference and near-ties resolve identically.
__global__ __launch_bounds__(256) void assign_kernel(const float* __restrict__ x,
                                                     const float* __restrict__ c,
                                                     float* __restrict__ out) {
    extern __shared__ float smem[];          // K*D centroids, then K squared norms
    float* sc = smem;
    float* csq = smem + K * D;

    // Cooperative load of centroids (coalesced float4)
    const float4* c4 = (const float4*)c;
    float4* sc4 = (float4*)sc;
    for (int i = threadIdx.x; i < (K * D) / 4; i += blockDim.x)
        sc4[i] = c4[i];
    __syncthreads();

    // c_sq[k]: separate rounded multiply then sequential adds (NO fma contraction),
    // matching jnp.sum(centroids*centroids, axis=1).
    if (threadIdx.x < K) {
        float s = 0.f;
        #pragma unroll
        for (int d = 0; d < D; d++) {
            float v = sc[threadIdx.x * D + d];
            s = __fadd_rn(s, __fmul_rn(v, v));
        }
        csq[threadIdx.x] = s;
    }
    __syncthreads();

    int i = blockIdx.x * blockDim.x + threadIdx.x;
    if (i >= NPTS) return;

    // Point coordinates in registers (coalesced float4 loads, 128B per warp-step)
    float xv[D];
    const float4* xr = (const float4*)(x + (size_t)i * D);
    #pragma unroll
    for (int j = 0; j < D / 4; j++) {
        float4 v = xr[j];
        xv[4 * j + 0] = v.x; xv[4 * j + 1] = v.y; xv[4 * j + 2] = v.z; xv[4 * j + 3] = v.w;
    }

    // x_sq: rounded squares then sequential adds (matches jnp.sum(x*x, axis=1))
    float x_sq = 0.f;
    #pragma unroll
    for (int d = 0; d < D; d++)
        x_sq = __fadd_rn(x_sq, __fmul_rn(xv[d], xv[d]));

    float best = __int_as_float(0x7f800000);  // +inf
    int bestk = 0;

    #pragma unroll 4
    for (int k = 0; k < K; k++) {
        const float4* cr = (const float4*)(sc + k * D);
        float dot = 0.f;
        // Sequential FMA chain over d, loads stay LDS.128 (1 LDS per 4 FMA).
        #pragma unroll
        for (int j = 0; j < D / 4; j++) {
            float4 cv = cr[j];
            dot = fmaf(xv[4 * j + 0], cv.x, dot);
            dot = fmaf(xv[4 * j + 1], cv.y, dot);
            dot = fmaf(xv[4 * j + 2], cv.z, dot);
            dot = fmaf(xv[4 * j + 3], cv.w, dot);
        }
        // (x_sq - 2*dot) + c_sq  in exact reference order; 2*dot is exact.
        float d_sq = __fadd_rn(__fsub_rn(x_sq, __fmul_rn(2.0f, dot)), csq[k]);
        if (d_sq < best) { best = d_sq; bestk = k; }  // strict < => first min, matches argmin
    }

    out[K * D + i] = (float)bestk;
}

extern "C" void kernel_launch(void* const* d_in, const int* in_sizes, int n_in,
                              void* d_out, int out_size) {
    const float* x = (const float*)d_in[0];
    const float* c = (const float*)d_in[1];
    float* out = (float*)d_out;

    const int smem_bytes = (K * D + K) * (int)sizeof(float);  // 66560 B
    cudaFuncSetAttribute(assign_kernel, cudaFuncAttributeMaxDynamicSharedMemorySize, smem_bytes);

    copy_centroids_kernel<<<(K * D + 255) / 256, 256>>>(c, out);
    assign_kernel<<<(NPTS + 255) / 256, 256, smem_bytes>>>(x, c, out);
}

// round 4
// speedup vs baseline: 1.2872x; 1.2872x over previous
#include <cuda_runtime.h>

#define NPTS 500000
#define K 256
#define D 64
#define TP 256   // points per block tile

// Copy centroids (echoed as first output of the tuple).
__global__ void copy_centroids_kernel(const float* __restrict__ c, float* __restrict__ out) {
    int i = blockIdx.x * blockDim.x + threadIdx.x;
    if (i < K * D) out[i] = c[i];
}

// Register-blocked assignment kernel.
// Each lane owns a 4-point x 8-centroid accumulator block (32 independent
// sequential-d FMA chains). x and centroids staged TRANSPOSED in smem so one
// LDS.128 serves 4 points / 4 centroids at the same d (conflict-free).
// Arithmetic replicates the reference bit-for-bit:
//   d_sq = ( x_sq - 2*dot ) + c_sq, dot = sequential-d FMA chain,
//   x_sq/c_sq = rounded squares + sequential adds.
__global__ __launch_bounds__(256) void assign_kernel(const float* __restrict__ x,
                                                     const float* __restrict__ c,
                                                     float* __restrict__ out) {
    extern __shared__ float smem[];
    float* sc  = smem;               // cT[64][256]
    float* sx  = smem + D * K;       // xT[64][256]
    float* scq = smem + 2 * D * K;   // c_sq[256]
    float* sxq = scq + K;            // x_sq[256]

    const int t = threadIdx.x;

    // ---- Stage centroids transposed + c_sq (thread t = centroid t) ----
    {
        const float4* crow = (const float4*)(c + t * D);
        float s = 0.f;
        #pragma unroll
        for (int d4 = 0; d4 < D / 4; d4++) {
            float4 v = crow[d4];
            sc[(4 * d4 + 0) * K + t] = v.x;
            sc[(4 * d4 + 1) * K + t] = v.y;
            sc[(4 * d4 + 2) * K + t] = v.z;
            sc[(4 * d4 + 3) * K + t] = v.w;
            s = __fadd_rn(s, __fmul_rn(v.x, v.x));
            s = __fadd_rn(s, __fmul_rn(v.y, v.y));
            s = __fadd_rn(s, __fmul_rn(v.z, v.z));
            s = __fadd_rn(s, __fmul_rn(v.w, v.w));
        }
        scq[t] = s;
    }

    // ---- Stage x tile transposed + x_sq (thread t = point base+t) ----
    {
        long pg = (long)blockIdx.x * TP + t;
        float s = 0.f;
        if (pg < NPTS) {
            const float4* xrow = (const float4*)(x + pg * D);
            #pragma unroll
            for (int d4 = 0; d4 < D / 4; d4++) {
                float4 v = xrow[d4];
                sx[(4 * d4 + 0) * K + t] = v.x;
                sx[(4 * d4 + 1) * K + t] = v.y;
                sx[(4 * d4 + 2) * K + t] = v.z;
                sx[(4 * d4 + 3) * K + t] = v.w;
                s = __fadd_rn(s, __fmul_rn(v.x, v.x));
                s = __fadd_rn(s, __fmul_rn(v.y, v.y));
                s = __fadd_rn(s, __fmul_rn(v.z, v.z));
                s = __fadd_rn(s, __fmul_rn(v.w, v.w));
            }
        } else {
            #pragma unroll
            for (int d4 = 0; d4 < D / 4; d4++) {
                sx[(4 * d4 + 0) * K + t] = 0.f;
                sx[(4 * d4 + 1) * K + t] = 0.f;
                sx[(4 * d4 + 2) * K + t] = 0.f;
                sx[(4 * d4 + 3) * K + t] = 0.f;
            }
        }
        sxq[t] = s;
    }
    __syncthreads();

    // ---- Compute: warp w covers points [w*32, w*32+32); lane = (pb, kb) ----
    const int w    = t >> 5;
    const int lane = t & 31;
    const int pb   = lane >> 2;   // 0..7 -> 4 points each
    const int kb   = lane & 3;    // 0..3 -> 8 centroids each per tile

    const int xoff = w * 32 + pb * 4;

    float xsqv[4];
    #pragma unroll
    for (int i = 0; i < 4; i++) xsqv[i] = sxq[xoff + i];

    float best[4];
    int   bestk[4];
    #pragma unroll
    for (int i = 0; i < 4; i++) { best[i] = __int_as_float(0x7f800000); bestk[i] = 0; }

    #pragma unroll 1
    for (int tile = 0; tile < K / 32; tile++) {
        const int kbase = tile * 32 + kb * 8;

        float acc[4][8];
        #pragma unroll
        for (int i = 0; i < 4; i++)
            #pragma unroll
            for (int j = 0; j < 8; j++) acc[i][j] = 0.f;

        #pragma unroll 8
        for (int d = 0; d < D; d++) {
            float4 xv = *(const float4*)(sx + d * K + xoff);
            float4 c0 = *(const float4*)(sc + d * K + kbase);
            float4 c1 = *(const float4*)(sc + d * K + kbase + 4);
            float xa[4] = {xv.x, xv.y, xv.z, xv.w};
            float ca[8] = {c0.x, c0.y, c0.z, c0.w, c1.x, c1.y, c1.z, c1.w};
            #pragma unroll
            for (int i = 0; i < 4; i++)
                #pragma unroll
                for (int j = 0; j < 8; j++)
                    acc[i][j] = fmaf(xa[i], ca[j], acc[i][j]);
        }

        #pragma unroll
        for (int j = 0; j < 8; j++) {
            float cq = scq[kbase + j];
            #pragma unroll
            for (int i = 0; i < 4; i++) {
                // (x_sq - 2*dot) via single-rounding fma (2*dot exact), then + c_sq
                float dsq = __fadd_rn(fmaf(acc[i][j], -2.0f, xsqv[i]), cq);
                if (dsq < best[i]) { best[i] = dsq; bestk[i] = kbase + j; }
            }
        }
    }

    // ---- Reduce across the 4 kb-lanes (butterfly), tie-break on smaller k ----
    #pragma unroll
    for (int i = 0; i < 4; i++) {
        #pragma unroll
        for (int off = 1; off <= 2; off <<= 1) {
            float ov = __shfl_xor_sync(0xffffffffu, best[i], off);
            int   ok = __shfl_xor_sync(0xffffffffu, bestk[i], off);
            if (ov < best[i] || (ov == best[i] && ok < bestk[i])) {
                best[i] = ov; bestk[i] = ok;
            }
        }
    }

    // ---- Store assignments (one kb-lane per point group) ----
    if (kb == 0) {
        long pg = (long)blockIdx.x * TP + xoff;
        #pragma unroll
        for (int i = 0; i < 4; i++)
            if (pg + i < NPTS) out[K * D + pg + i] = (float)bestk[i];
    }
}

extern "C" void kernel_launch(void* const* d_in, const int* in_sizes, int n_in,
                              void* d_out, int out_size) {
    const float* x = (const float*)d_in[0];
    const float* c = (const float*)d_in[1];
    float* out = (float*)d_out;

    const int smem_bytes = (2 * D * K + 2 * K) * (int)sizeof(float);  // 133120 B
    cudaFuncSetAttribute(assign_kernel, cudaFuncAttributeMaxDynamicSharedMemorySize, smem_bytes);

    copy_centroids_kernel<<<(K * D + 255) / 256, 256>>>(c, out);
    assign_kernel<<<(NPTS + TP - 1) / TP, 256, smem_bytes>>>(x, c, out);
}

// round 5
// speedup vs baseline: 1.5007x; 1.1658x over previous
#include <cuda_runtime.h>

#define NPTS 500000
#define K 256
#define D 64
#define TP 512            // points per block tile
#define NTHREADS 512

// Copy centroids (echoed as first output of the tuple).
__global__ void copy_centroids_kernel(const float* __restrict__ c, float* __restrict__ out) {
    int i = blockIdx.x * blockDim.x + threadIdx.x;
    if (i < K * D) out[i] = c[i];
}

// 8x8 register-tiled assignment kernel.
// Lane owns 8 points x 8 centroids = 64 independent sequential-d FMA chains.
// Per d per warp: 2 x-LDS.128 + 2 c-LDS.128 = 16 crossbar wavefronts per 64 FMA
// (1:4 -> crossbar and FMA pipes saturate together).
// Bit-identical arithmetic to the reference:
//   d_sq = (x_sq - 2*dot) + c_sq; dot = ascending-d FMA chain;
//   x_sq/c_sq = rounded squares + sequential adds.
__global__ __launch_bounds__(NTHREADS) void assign_kernel(const float* __restrict__ x,
                                                          const float* __restrict__ c,
                                                          float* __restrict__ out) {
    extern __shared__ float smem[];
    float* sc  = smem;                    // cT[64][256]   (64 KB)
    float* sx  = smem + D * K;            // xT[64][512]   (128 KB)
    float* scq = smem + D * K + D * TP;   // c_sq[256]
    float* sxq = scq + K;                 // x_sq[512]

    const int t = threadIdx.x;

    // ---- Stage centroids transposed + c_sq (threads 0..255, one per centroid) ----
    if (t < K) {
        const float4* crow = (const float4*)(c + t * D);
        float s = 0.f;
        #pragma unroll
        for (int d4 = 0; d4 < D / 4; d4++) {
            float4 v = crow[d4];
            sc[(4 * d4 + 0) * K + t] = v.x;
            sc[(4 * d4 + 1) * K + t] = v.y;
            sc[(4 * d4 + 2) * K + t] = v.z;
            sc[(4 * d4 + 3) * K + t] = v.w;
            s = __fadd_rn(s, __fmul_rn(v.x, v.x));
            s = __fadd_rn(s, __fmul_rn(v.y, v.y));
            s = __fadd_rn(s, __fmul_rn(v.z, v.z));
            s = __fadd_rn(s, __fmul_rn(v.w, v.w));
        }
        scq[t] = s;
    }

    // ---- Stage x tile transposed + x_sq (thread t = point base+t) ----
    {
        long pg = (long)blockIdx.x * TP + t;
        float s = 0.f;
        if (pg < NPTS) {
            const float4* xrow = (const float4*)(x + pg * D);
            #pragma unroll
            for (int d4 = 0; d4 < D / 4; d4++) {
                float4 v = xrow[d4];
                sx[(4 * d4 + 0) * TP + t] = v.x;
                sx[(4 * d4 + 1) * TP + t] = v.y;
                sx[(4 * d4 + 2) * TP + t] = v.z;
                sx[(4 * d4 + 3) * TP + t] = v.w;
                s = __fadd_rn(s, __fmul_rn(v.x, v.x));
                s = __fadd_rn(s, __fmul_rn(v.y, v.y));
                s = __fadd_rn(s, __fmul_rn(v.z, v.z));
                s = __fadd_rn(s, __fmul_rn(v.w, v.w));
            }
        } else {
            #pragma unroll
            for (int d4 = 0; d4 < D / 4; d4++) {
                sx[(4 * d4 + 0) * TP + t] = 0.f;
                sx[(4 * d4 + 1) * TP + t] = 0.f;
                sx[(4 * d4 + 2) * TP + t] = 0.f;
                sx[(4 * d4 + 3) * TP + t] = 0.f;
            }
        }
        sxq[t] = s;
    }
    __syncthreads();

    // ---- Compute: warp w covers points [w*32, w*32+32) ----
    // lane = (pb, kb): pb = lane>>3 (4 groups x 8 points), kb = lane&7 (8 groups x 8 k)
    const int w    = t >> 5;
    const int lane = t & 31;
    const int pb   = lane >> 3;
    const int kb   = lane & 7;

    const int xoff = w * 32 + pb * 8;

    float xsqv[8];
    #pragma unroll
    for (int i = 0; i < 8; i++) xsqv[i] = sxq[xoff + i];

    float best[8];
    int   bestk[8];
    #pragma unroll
    for (int i = 0; i < 8; i++) { best[i] = __int_as_float(0x7f800000); bestk[i] = 0; }

    #pragma unroll 1
    for (int tile = 0; tile < K / 64; tile++) {        // 4 tiles of 64 k
        const int kbase = tile * 64 + kb * 8;

        float acc[8][8];
        #pragma unroll
        for (int i = 0; i < 8; i++)
            #pragma unroll
            for (int j = 0; j < 8; j++) acc[i][j] = 0.f;

        #pragma unroll 4
        for (int d = 0; d < D; d++) {
            float4 x0 = *(const float4*)(sx + d * TP + xoff);
            float4 x1 = *(const float4*)(sx + d * TP + xoff + 4);
            float4 c0 = *(const float4*)(sc + d * K + kbase);
            float4 c1 = *(const float4*)(sc + d * K + kbase + 4);
            float xa[8] = {x0.x, x0.y, x0.z, x0.w, x1.x, x1.y, x1.z, x1.w};
            float ca[8] = {c0.x, c0.y, c0.z, c0.w, c1.x, c1.y, c1.z, c1.w};
            #pragma unroll
            for (int i = 0; i < 8; i++)
                #pragma unroll
                for (int j = 0; j < 8; j++)
                    acc[i][j] = fmaf(xa[i], ca[j], acc[i][j]);
        }

        #pragma unroll
        for (int j = 0; j < 8; j++) {
            float cq = scq[kbase + j];
            #pragma unroll
            for (int i = 0; i < 8; i++) {
                // (x_sq - 2*dot) single-rounded via fma (2*dot exact), then + c_sq
                float dsq = __fadd_rn(fmaf(acc[i][j], -2.0f, xsqv[i]), cq);
                if (dsq < best[i]) { best[i] = dsq; bestk[i] = kbase + j; }
            }
        }
    }

    // ---- Reduce across the 8 kb-lanes (butterfly), tie-break on smaller k ----
    #pragma unroll
    for (int i = 0; i < 8; i++) {
        #pragma unroll
        for (int off = 1; off <= 4; off <<= 1) {
            float ov = __shfl_xor_sync(0xffffffffu, best[i], off);
            int   ok = __shfl_xor_sync(0xffffffffu, bestk[i], off);
            if (ov < best[i] || (ov == best[i] && ok < bestk[i])) {
                best[i] = ov; bestk[i] = ok;
            }
        }
    }

    // ---- Store assignments (kb==0 lane of each pb group writes its 8 points) ----
    if (kb == 0) {
        long pg = (long)blockIdx.x * TP + xoff;
        #pragma unroll
        for (int i = 0; i < 8; i++)
            if (pg + i < NPTS) out[K * D + pg + i] = (float)bestk[i];
    }
}

extern "C" void kernel_launch(void* const* d_in, const int* in_sizes, int n_in,
                              void* d_out, int out_size) {
    const float* x = (const float*)d_in[0];
    const float* c = (const float*)d_in[1];
    float* out = (float*)d_out;

    const int smem_bytes = (D * K + D * TP + K + TP) * (int)sizeof(float);  // 199680 B
    cudaFuncSetAttribute(assign_kernel, cudaFuncAttributeMaxDynamicSharedMemorySize, smem_bytes);

    copy_centroids_kernel<<<(K * D + 255) / 256, 256>>>(c, out);
    assign_kernel<<<(NPTS + TP - 1) / TP, NTHREADS, smem_bytes>>>(x, c, out);
}

// round 6
// speedup vs baseline: 1.5728x; 1.0481x over previous
#include <cuda_runtime.h>

#define NPTS 500000
#define K 256
#define D 64
#define TP 512            // points per block tile
#define NTHREADS 256

__global__ void copy_centroids_kernel(const float* __restrict__ c, float* __restrict__ out) {
    int i = blockIdx.x * blockDim.x + threadIdx.x;
    if (i < K * D) out[i] = c[i];
}

// 8x16 register-tiled assignment kernel with packed f32x2 FMA.
// Lane owns 8 points x 16 centroids = 128 fp32 accumulators held as 64 f32x2.
// fma.rn.f32x2 = two independent round-to-nearest fp32 FMAs -> bit-identical
// to the scalar fmaf chain. Epilogue: d_sq = fadd(fma(dot,-2,x_sq), c_sq),
// identical to the reference's (x_sq - 2*dot) + c_sq.
__global__ __launch_bounds__(NTHREADS) void assign_kernel(const float* __restrict__ x,
                                                          const float* __restrict__ c,
                                                          float* __restrict__ out) {
    extern __shared__ float smem[];
    float* sc  = smem;                    // cT[64][256]
    float* sx  = smem + D * K;            // xT[64][512]
    float* scq = smem + D * K + D * TP;   // c_sq[256]
    float* sxq = scq + K;                 // x_sq[512]

    const int t = threadIdx.x;

    // ---- Stage centroids transposed + c_sq (one thread per centroid) ----
    {
        const float4* crow = (const float4*)(c + t * D);
        float s = 0.f;
        #pragma unroll
        for (int d4 = 0; d4 < D / 4; d4++) {
            float4 v = crow[d4];
            sc[(4 * d4 + 0) * K + t] = v.x;
            sc[(4 * d4 + 1) * K + t] = v.y;
            sc[(4 * d4 + 2) * K + t] = v.z;
            sc[(4 * d4 + 3) * K + t] = v.w;
            s = __fadd_rn(s, __fmul_rn(v.x, v.x));
            s = __fadd_rn(s, __fmul_rn(v.y, v.y));
            s = __fadd_rn(s, __fmul_rn(v.z, v.z));
            s = __fadd_rn(s, __fmul_rn(v.w, v.w));
        }
        scq[t] = s;
    }

    // ---- Stage x tile transposed + x_sq (2 points per thread) ----
    #pragma unroll
    for (int rep = 0; rep < TP / NTHREADS; rep++) {
        int  pl = rep * NTHREADS + t;
        long pg = (long)blockIdx.x * TP + pl;
        float s = 0.f;
        if (pg < NPTS) {
            const float4* xrow = (const float4*)(x + pg * D);
            #pragma unroll
            for (int d4 = 0; d4 < D / 4; d4++) {
                float4 v = xrow[d4];
                sx[(4 * d4 + 0) * TP + pl] = v.x;
                sx[(4 * d4 + 1) * TP + pl] = v.y;
                sx[(4 * d4 + 2) * TP + pl] = v.z;
                sx[(4 * d4 + 3) * TP + pl] = v.w;
                s = __fadd_rn(s, __fmul_rn(v.x, v.x));
                s = __fadd_rn(s, __fmul_rn(v.y, v.y));
                s = __fadd_rn(s, __fmul_rn(v.z, v.z));
                s = __fadd_rn(s, __fmul_rn(v.w, v.w));
            }
        } else {
            #pragma unroll
            for (int d4 = 0; d4 < D / 4; d4++) {
                sx[(4 * d4 + 0) * TP + pl] = 0.f;
                sx[(4 * d4 + 1) * TP + pl] = 0.f;
                sx[(4 * d4 + 2) * TP + pl] = 0.f;
                sx[(4 * d4 + 3) * TP + pl] = 0.f;
            }
        }
        sxq[pl] = s;
    }
    __syncthreads();

    // ---- Compute: warp w covers points [w*64, w*64+64) ----
    // lane = (pb, kb): pb = lane>>2 (8 groups x 8 points), kb = lane&3 (4 groups x 16 k)
    const int w    = t >> 5;
    const int lane = t & 31;
    const int pb   = lane >> 2;
    const int kb   = lane & 3;

    const int xoff = w * 64 + pb * 8;

    float xsqv[8];
    #pragma unroll
    for (int i = 0; i < 8; i++) xsqv[i] = sxq[xoff + i];

    float best[8];
    int   bestk[8];
    #pragma unroll
    for (int i = 0; i < 8; i++) { best[i] = __int_as_float(0x7f800000); bestk[i] = 0; }

    #pragma unroll 1
    for (int tile = 0; tile < K / 64; tile++) {
        const int kbase = tile * 64 + kb * 16;

        // 8 points x 16 k as 8x8 packed f32x2 (pairs over adjacent k)
        unsigned long long acc2[8][8];
        #pragma unroll
        for (int i = 0; i < 8; i++)
            #pragma unroll
            for (int j = 0; j < 8; j++) acc2[i][j] = 0ull;

        #pragma unroll 4
        for (int d = 0; d < D; d++) {
            float4 x0 = *(const float4*)(sx + d * TP + xoff);
            float4 x1 = *(const float4*)(sx + d * TP + xoff + 4);
            // 16 c floats = 8 packed pairs (adjacent k), already in pair order
            const ulonglong2* cp = (const ulonglong2*)(sc + d * K + kbase);
            ulonglong2 cq0 = cp[0], cq1 = cp[1], cq2 = cp[2], cq3 = cp[3];
            unsigned long long cb[8] = {cq0.x, cq0.y, cq1.x, cq1.y,
                                        cq2.x, cq2.y, cq3.x, cq3.y};
            float xa[8] = {x0.x, x0.y, x0.z, x0.w, x1.x, x1.y, x1.z, x1.w};
            #pragma unroll
            for (int i = 0; i < 8; i++) {
                unsigned long long xd;  // duplicate x_i into both halves
                asm("mov.b64 %0, {%1, %1};" : "=l"(xd) : "f"(xa[i]));
                #pragma unroll
                for (int j = 0; j < 8; j++)
                    asm("fma.rn.f32x2 %0, %1, %2, %0;"
                        : "+l"(acc2[i][j]) : "l"(xd), "l"(cb[j]));
            }
        }

        #pragma unroll
        for (int j = 0; j < 8; j++) {
            float cq_lo = scq[kbase + 2 * j];
            float cq_hi = scq[kbase + 2 * j + 1];
            #pragma unroll
            for (int i = 0; i < 8; i++) {
                float dlo, dhi;
                asm("mov.b64 {%0, %1}, %2;" : "=f"(dlo), "=f"(dhi) : "l"(acc2[i][j]));
                float dsq_lo = __fadd_rn(fmaf(dlo, -2.0f, xsqv[i]), cq_lo);
                float dsq_hi = __fadd_rn(fmaf(dhi, -2.0f, xsqv[i]), cq_hi);
                if (dsq_lo < best[i]) { best[i] = dsq_lo; bestk[i] = kbase + 2 * j; }
                if (dsq_hi < best[i]) { best[i] = dsq_hi; bestk[i] = kbase + 2 * j + 1; }
            }
        }
    }

    // ---- Reduce across the 4 kb-lanes (butterfly), tie-break on smaller k ----
    #pragma unroll
    for (int i = 0; i < 8; i++) {
        #pragma unroll
        for (int off = 1; off <= 2; off <<= 1) {
            float ov = __shfl_xor_sync(0xffffffffu, best[i], off);
            int   ok = __shfl_xor_sync(0xffffffffu, bestk[i], off);
            if (ov < best[i] || (ov == best[i] && ok < bestk[i])) {
                best[i] = ov; bestk[i] = ok;
            }
        }
    }

    // ---- Store assignments (kb==0 lane of each pb group writes its 8 points) ----
    if (kb == 0) {
        long pg = (long)blockIdx.x * TP + xoff;
        #pragma unroll
        for (int i = 0; i < 8; i++)
            if (pg + i < NPTS) out[K * D + pg + i] = (float)bestk[i];
    }
}

extern "C" void kernel_launch(void* const* d_in, const int* in_sizes, int n_in,
                              void* d_out, int out_size) {
    const float* x = (const float*)d_in[0];
    const float* c = (const float*)d_in[1];
    float* out = (float*)d_out;

    const int smem_bytes = (D * K + D * TP + K + TP) * (int)sizeof(float);  // 199680 B
    cudaFuncSetAttribute(assign_kernel, cudaFuncAttributeMaxDynamicSharedMemorySize, smem_bytes);

    copy_centroids_kernel<<<(K * D + 255) / 256, 256>>>(c, out);
    assign_kernel<<<(NPTS + TP - 1) / TP, NTHREADS, smem_bytes>>>(x, c, out);
}